// round 10
// baseline (speedup 1.0000x reference)
#include <cuda_runtime.h>
#include <cuda_bf16.h>
#include <cstdint>

// Problem constants
#define B_     64
#define H_     512
#define W_     512
#define C_     3
#define G_     64
#define K_     3
#define D_IN   (K_*G_*G_*C_)   // 36864
#define HG_    128
#define HL_    128

// GEMM split-K config
#define NCHUNK 288
#define DC     128             // K-dims per CTA chunk (NCHUNK*DC == D_IN)

// Scratch (device globals): phi as split bf16 hi/lo (compensated GEMM inputs)
__device__ __nv_bfloat16 g_phiH[(size_t)B_ * D_IN];   // 4.7 MB
__device__ __nv_bfloat16 g_phiL[(size_t)B_ * D_IN];   // 4.7 MB
__device__ float g_part[(size_t)NCHUNK * B_ * HG_];   // 9.4 MB

__device__ __forceinline__ uint32_t smem_u32(const void* p) {
    uint32_t a;
    asm("{ .reg .u64 t; cvta.to.shared.u64 t, %1; cvt.u32.u64 %0, t; }"
        : "=r"(a) : "l"(p));
    return a;
}

__device__ __forceinline__ void store_phi(size_t off, float v) {
    __nv_bfloat16 h = __float2bfloat16(v);
    __nv_bfloat16 e = __float2bfloat16(v - __bfloat162float(h));
    g_phiH[off] = h;
    g_phiL[off] = e;
}

// ---------------------------------------------------------------------------
// Kernel 1: fused multi-scale glimpse extraction + avg pooling
// (R6/R9 structure — measured best — with bf16 hi/lo phi output)
// ---------------------------------------------------------------------------
__global__ __launch_bounds__(192) void extract_kernel(
    const float* __restrict__ x, const float* __restrict__ l)
{
    __shared__ float buf[4 * 768];

    const int gy2 = blockIdx.x;
    const int b   = blockIdx.y;
    const int tid = threadIdx.x;

    // denormalize coords exactly like reference: trunc((0.5*(l+1))*512)
    const float lx = __ldg(&l[b * 2 + 0]);
    const float ly = __ldg(&l[b * 2 + 1]);
    const int cx = (int)((0.5f * (lx + 1.0f)) * 512.0f);
    const int cy = (int)((0.5f * (ly + 1.0f)) * 512.0f);
    const int xs = cx - 128;
    const int ys = cy - 128 + gy2 * 4;

    const int jlo = (xs < 0 ? -xs : 0) * 3;
    const int xe  = xs + 256;
    const int jhi = ((xe > W_ ? W_ : xe) - xs) * 3;

    // stage 4 contiguous source rows (zero-filled OOB), scalar loads
    #pragma unroll
    for (int rr = 0; rr < 4; rr++) {
        const int y = ys + rr;
        const bool yok = (y >= 0) && (y < H_);
        const float* rowp = x + (((size_t)b * H_ + y) * W_ + xs) * C_;
        #pragma unroll
        for (int it = 0; it < 4; it++) {
            const int j = tid + it * 192;
            float v = 0.0f;
            if (yok && j >= jlo && j < jhi) v = __ldg(rowp + j);
            buf[rr * 768 + j] = v;
        }
    }
    __syncthreads();

    const int gx = tid / 3;
    const int c  = tid - gx * 3;
    const size_t phiB = (size_t)b * D_IN;

    // ---- k=2: pool 4x4 ----
    {
        float sum = 0.0f;
        #pragma unroll
        for (int dy = 0; dy < 4; dy++)
            #pragma unroll
            for (int dx = 0; dx < 4; dx++)
                sum += buf[dy * 768 + (gx * 4 + dx) * 3 + c];
        store_phi(phiB + (2 * G_ + gy2) * (G_ * C_) + tid, sum * (1.0f / 16.0f));
    }

    // ---- k=1: two output rows, pool 2x2 over central 128 cols ----
    if (gy2 >= 16 && gy2 < 48) {
        #pragma unroll
        for (int h = 0; h < 2; h++) {
            const int gy1 = 2 * gy2 - 32 + h;
            float sum = 0.0f;
            #pragma unroll
            for (int dy = 0; dy < 2; dy++)
                #pragma unroll
                for (int dx = 0; dx < 2; dx++)
                    sum += buf[(2 * h + dy) * 768 + (64 + gx * 2 + dx) * 3 + c];
            store_phi(phiB + (G_ + gy1) * (G_ * C_) + tid, sum * 0.25f);
        }
    }

    // ---- k=0: four output rows, direct copy of central 64 cols ----
    if (gy2 >= 24 && gy2 < 40) {
        #pragma unroll
        for (int rr = 0; rr < 4; rr++) {
            const int gy0 = 4 * gy2 - 96 + rr;
            store_phi(phiB + gy0 * (G_ * C_) + tid, buf[rr * 768 + (96 + gx) * 3 + c]);
        }
    }
}

// ---------------------------------------------------------------------------
// Kernel 2: split-K GEMM via mma.sync bf16, bf16x3 compensated:
// D = Ah*Bh + Ah*Bl + Al*Bh, fp32 accumulate.
// Grid 288, 256 threads (8 warps, warp = 16m x 64n), DC=128 single slab.
// smem 104448B -> 2 CTAs co-resident per SM: one CTA's fill overlaps the
// other's MMA compute (latency hiding via co-scheduling, not intra-CTA).
// ---------------------------------------------------------------------------
#define KSTR   136                       // padded K stride in bf16 (272B rows)
#define A_TILE (64 * KSTR * 2)           // 17408 B
#define B_TILE (128 * KSTR * 2)          // 34816 B
#define OFF_AH 0
#define OFF_AL A_TILE
#define OFF_BH (2 * A_TILE)
#define OFF_BL (2 * A_TILE + B_TILE)
#define SMEM_GEMM (2 * A_TILE + 2 * B_TILE)   // 104448 B

__device__ __forceinline__ void ldsm_x4(uint32_t a[4], uint32_t addr) {
    asm volatile("ldmatrix.sync.aligned.m8n8.x4.shared.b16 {%0,%1,%2,%3}, [%4];"
                 : "=r"(a[0]), "=r"(a[1]), "=r"(a[2]), "=r"(a[3]) : "r"(addr));
}
__device__ __forceinline__ void mma_bf16(
    float c[4], const uint32_t a[4], uint32_t b0, uint32_t b1)
{
    asm volatile(
        "mma.sync.aligned.m16n8k16.row.col.f32.bf16.bf16.f32 "
        "{%0,%1,%2,%3}, {%4,%5,%6,%7}, {%8,%9}, {%0,%1,%2,%3};"
        : "+f"(c[0]), "+f"(c[1]), "+f"(c[2]), "+f"(c[3])
        : "r"(a[0]), "r"(a[1]), "r"(a[2]), "r"(a[3]), "r"(b0), "r"(b1));
}
__device__ __forceinline__ uint32_t hi_lo_pack(float v0, float v1, uint32_t& lo_out)
{
    __nv_bfloat16 h0 = __float2bfloat16(v0);
    __nv_bfloat16 h1 = __float2bfloat16(v1);
    __nv_bfloat16 e0 = __float2bfloat16(v0 - __bfloat162float(h0));
    __nv_bfloat16 e1 = __float2bfloat16(v1 - __bfloat162float(h1));
    __nv_bfloat162 hp; hp.x = h0; hp.y = h1;
    __nv_bfloat162 lp; lp.x = e0; lp.y = e1;
    lo_out = *reinterpret_cast<uint32_t*>(&lp);
    return *reinterpret_cast<uint32_t*>(&hp);
}

__global__ __launch_bounds__(256, 2) void gemm_mma_kernel(const float* __restrict__ W1)
{
    extern __shared__ char smem[];
    const uint32_t sb = smem_u32(smem);
    const int tid  = threadIdx.x;
    const int wid  = tid >> 5;
    const int lane = tid & 31;
    const int d0   = blockIdx.x * DC;

    // ---- fill A (64 x 128 bf16) hi/lo: straight 16B copies ----
    for (int idx = tid; idx < 64 * 16; idx += 256) {
        const int m = idx >> 4;
        const int i = idx & 15;                    // 16B chunk (8 bf16)
        const size_t src = (size_t)m * D_IN + d0 + i * 8;
        const int off = m * (KSTR * 2) + i * 16;
        *reinterpret_cast<uint4*>(smem + OFF_AH + off) =
            *reinterpret_cast<const uint4*>(&g_phiH[src]);
        *reinterpret_cast<uint4*>(smem + OFF_AL + off) =
            *reinterpret_cast<const uint4*>(&g_phiL[src]);
    }

    // ---- fill B^T (128 n x 128 k): B[n][k] = W1[d0+k][n], hi/lo ----
    for (int idx = tid; idx < 64 * 128; idx += 256) {
        const int kk = idx >> 7;
        const int n  = idx & 127;
        const float v0 = __ldg(&W1[(size_t)(d0 + 2 * kk)     * HG_ + n]);
        const float v1 = __ldg(&W1[(size_t)(d0 + 2 * kk + 1) * HG_ + n]);
        uint32_t lo, hi = hi_lo_pack(v0, v1, lo);
        const int off = n * (KSTR * 2) + kk * 4;
        *reinterpret_cast<uint32_t*>(smem + OFF_BH + off) = hi;
        *reinterpret_cast<uint32_t*>(smem + OFF_BL + off) = lo;
    }
    __syncthreads();

    // ---- warp tiling: mt = wid>>1 (m16 tiles), nh = wid&1 (n64 halves) ----
    const int mt = wid >> 1;
    const int nh = wid & 1;

    const uint32_t aRel = (uint32_t)((mt * 16 + (lane & 15)) * (KSTR * 2)
                                     + (lane >> 4) * 16);
    const uint32_t bRel = (uint32_t)((nh * 64 + ((lane >> 4) * 8) + (lane & 7)) * (KSTR * 2)
                                     + (((lane >> 3) & 1) * 16));

    float acc[8][4];
    #pragma unroll
    for (int nt = 0; nt < 8; nt++)
        #pragma unroll
        for (int j = 0; j < 4; j++) acc[nt][j] = 0.0f;

    // ---- 3 compensated passes ----
    #pragma unroll
    for (int pass = 0; pass < 3; pass++) {
        const uint32_t aBase = sb + ((pass == 2) ? OFF_AL : OFF_AH) + aRel;
        const uint32_t bBase = sb + ((pass == 1) ? OFF_BL : OFF_BH) + bRel;
        #pragma unroll
        for (int kt = 0; kt < 8; kt++) {
            uint32_t a[4];
            ldsm_x4(a, aBase + kt * 32);
            #pragma unroll
            for (int np = 0; np < 4; np++) {      // pairs of n-tiles
                uint32_t bq[4];
                ldsm_x4(bq, bBase + np * 16 * (KSTR * 2) + kt * 32);
                mma_bf16(acc[np * 2 + 0], a, bq[0], bq[1]);
                mma_bf16(acc[np * 2 + 1], a, bq[2], bq[3]);
            }
        }
    }

    // ---- epilogue: write 64x128 partial tile ----
    float* part = &g_part[(size_t)blockIdx.x * (B_ * HG_)];
    const int qid = lane >> 2;
    const int tq  = lane & 3;
    const int row0 = mt * 16 + qid;
    #pragma unroll
    for (int nt = 0; nt < 8; nt++) {
        const int col = nh * 64 + nt * 8 + tq * 2;
        float2 v0; v0.x = acc[nt][0]; v0.y = acc[nt][1];
        float2 v1; v1.x = acc[nt][2]; v1.y = acc[nt][3];
        *reinterpret_cast<float2*>(part + row0 * HG_ + col) = v0;
        *reinterpret_cast<float2*>(part + (row0 + 8) * HG_ + col) = v1;
    }
}

// ---------------------------------------------------------------------------
// Kernel 3: reduce partials + bias + relu + l-branch.
// ---------------------------------------------------------------------------
__global__ __launch_bounds__(512) void finalize_kernel(
    const float* __restrict__ l, const float* __restrict__ b1,
    const float* __restrict__ W2, const float* __restrict__ b2,
    float* __restrict__ out)
{
    __shared__ float red[4][HG_];
    const int b = blockIdx.x;
    const int tid = threadIdx.x;
    const int h = tid & 127;
    const int p = tid >> 7;

    float s = 0.0f;
    #pragma unroll 9
    for (int c = p; c < NCHUNK; c += 4)
        s += g_part[(size_t)c * (B_ * HG_) + b * HG_ + h];
    red[p][h] = s;
    __syncthreads();

    if (p == 0) {
        const float v = red[0][h] + red[1][h] + red[2][h] + red[3][h] + b1[h];
        out[b * (HG_ + HL_) + h] = fmaxf(v, 0.0f);
        const float lw = l[b * 2 + 0] * W2[h] + l[b * 2 + 1] * W2[HL_ + h] + b2[h];
        out[b * (HG_ + HL_) + HG_ + h] = fmaxf(lw, 0.0f);
    }
}

// ---------------------------------------------------------------------------
extern "C" void kernel_launch(void* const* d_in, const int* in_sizes, int n_in,
                              void* d_out, int out_size)
{
    const float* x  = (const float*)d_in[0];
    const float* l  = (const float*)d_in[1];
    const float* W1 = (const float*)d_in[2];
    const float* b1 = (const float*)d_in[3];
    const float* W2 = (const float*)d_in[4];
    const float* b2 = (const float*)d_in[5];
    float* out = (float*)d_out;

    static bool attr_set = false;
    if (!attr_set) {
        cudaFuncSetAttribute(gemm_mma_kernel,
                             cudaFuncAttributeMaxDynamicSharedMemorySize, SMEM_GEMM);
        attr_set = true;
    }

    dim3 eg(G_, B_);
    extract_kernel<<<eg, 192>>>(x, l);
    gemm_mma_kernel<<<NCHUNK, 256, SMEM_GEMM>>>(W1);
    finalize_kernel<<<B_, 512>>>(l, b1, W2, b2, out);
}

// round 11
// speedup vs baseline: 1.0651x; 1.0651x over previous
#include <cuda_runtime.h>
#include <cuda_fp16.h>
#include <cstdint>

// Problem constants
#define B_     64
#define H_     512
#define W_     512
#define C_     3
#define G_     64
#define K_     3
#define D_IN   (K_*G_*G_*C_)   // 36864
#define HG_    128
#define HL_    128

// GEMM split-K config
#define NCHUNK 144
#define DC     256             // K-dims per CTA chunk (NCHUNK*DC == D_IN)

// Scratch (device globals): phi as split fp16 hi/lo (2-pass compensated GEMM)
__device__ __half g_phiH[(size_t)B_ * D_IN];          // 4.7 MB
__device__ __half g_phiL[(size_t)B_ * D_IN];          // 4.7 MB
__device__ float g_part[(size_t)NCHUNK * B_ * HG_];   // 4.7 MB

__device__ __forceinline__ uint32_t smem_u32(const void* p) {
    uint32_t a;
    asm("{ .reg .u64 t; cvta.to.shared.u64 t, %1; cvt.u32.u64 %0, t; }"
        : "=r"(a) : "l"(p));
    return a;
}

__device__ __forceinline__ void store_phi(size_t off, float v) {
    __half h = __float2half_rn(v);
    __half e = __float2half_rn(v - __half2float(h));
    g_phiH[off] = h;
    g_phiL[off] = e;
}

// ---------------------------------------------------------------------------
// Kernel 1: fused multi-scale glimpse extraction + avg pooling
// (R6/R9 structure — measured best — emitting fp16 hi/lo phi)
// ---------------------------------------------------------------------------
__global__ __launch_bounds__(192) void extract_kernel(
    const float* __restrict__ x, const float* __restrict__ l)
{
    __shared__ float buf[4 * 768];

    const int gy2 = blockIdx.x;
    const int b   = blockIdx.y;
    const int tid = threadIdx.x;

    // denormalize coords exactly like reference: trunc((0.5*(l+1))*512)
    const float lx = __ldg(&l[b * 2 + 0]);
    const float ly = __ldg(&l[b * 2 + 1]);
    const int cx = (int)((0.5f * (lx + 1.0f)) * 512.0f);
    const int cy = (int)((0.5f * (ly + 1.0f)) * 512.0f);
    const int xs = cx - 128;
    const int ys = cy - 128 + gy2 * 4;

    const int jlo = (xs < 0 ? -xs : 0) * 3;
    const int xe  = xs + 256;
    const int jhi = ((xe > W_ ? W_ : xe) - xs) * 3;

    // stage 4 contiguous source rows (zero-filled OOB), scalar loads
    #pragma unroll
    for (int rr = 0; rr < 4; rr++) {
        const int y = ys + rr;
        const bool yok = (y >= 0) && (y < H_);
        const float* rowp = x + (((size_t)b * H_ + y) * W_ + xs) * C_;
        #pragma unroll
        for (int it = 0; it < 4; it++) {
            const int j = tid + it * 192;
            float v = 0.0f;
            if (yok && j >= jlo && j < jhi) v = __ldg(rowp + j);
            buf[rr * 768 + j] = v;
        }
    }
    __syncthreads();

    const int gx = tid / 3;
    const int c  = tid - gx * 3;
    const size_t phiB = (size_t)b * D_IN;

    // ---- k=2: pool 4x4 ----
    {
        float sum = 0.0f;
        #pragma unroll
        for (int dy = 0; dy < 4; dy++)
            #pragma unroll
            for (int dx = 0; dx < 4; dx++)
                sum += buf[dy * 768 + (gx * 4 + dx) * 3 + c];
        store_phi(phiB + (2 * G_ + gy2) * (G_ * C_) + tid, sum * (1.0f / 16.0f));
    }

    // ---- k=1: two output rows, pool 2x2 over central 128 cols ----
    if (gy2 >= 16 && gy2 < 48) {
        #pragma unroll
        for (int h = 0; h < 2; h++) {
            const int gy1 = 2 * gy2 - 32 + h;
            float sum = 0.0f;
            #pragma unroll
            for (int dy = 0; dy < 2; dy++)
                #pragma unroll
                for (int dx = 0; dx < 2; dx++)
                    sum += buf[(2 * h + dy) * 768 + (64 + gx * 2 + dx) * 3 + c];
            store_phi(phiB + (G_ + gy1) * (G_ * C_) + tid, sum * 0.25f);
        }
    }

    // ---- k=0: four output rows, direct copy of central 64 cols ----
    if (gy2 >= 24 && gy2 < 40) {
        #pragma unroll
        for (int rr = 0; rr < 4; rr++) {
            const int gy0 = 4 * gy2 - 96 + rr;
            store_phi(phiB + gy0 * (G_ * C_) + tid, buf[rr * 768 + (96 + gx) * 3 + c]);
        }
    }
}

// ---------------------------------------------------------------------------
// Kernel 2: split-K GEMM via mma.sync fp16, 2-pass compensated:
// D = Ah*B + Al*B (A = phi split fp16 hi/lo; B = W1 single fp16).
// Residual error = B's fp16 rounding (~2^-11), well under the 1e-3 gate.
// Grid 144, 512 threads (16 warps, warp = 16m x 32n). DC=256 as 2 slabs.
// ---------------------------------------------------------------------------
#define KSTR   136                       // padded K stride in fp16 (272B rows)
#define A_TILE (64 * KSTR * 2)           // 17408 B
#define B_TILE (128 * KSTR * 2)          // 34816 B
#define OFF_AH 0
#define OFF_AL A_TILE
#define OFF_B  (2 * A_TILE)
#define SMEM_GEMM (2 * A_TILE + B_TILE)  // 69632 B

__device__ __forceinline__ void ldsm_x4(uint32_t a[4], uint32_t addr) {
    asm volatile("ldmatrix.sync.aligned.m8n8.x4.shared.b16 {%0,%1,%2,%3}, [%4];"
                 : "=r"(a[0]), "=r"(a[1]), "=r"(a[2]), "=r"(a[3]) : "r"(addr));
}
__device__ __forceinline__ void mma_fp16(
    float c[4], const uint32_t a[4], uint32_t b0, uint32_t b1)
{
    asm volatile(
        "mma.sync.aligned.m16n8k16.row.col.f32.f16.f16.f32 "
        "{%0,%1,%2,%3}, {%4,%5,%6,%7}, {%8,%9}, {%0,%1,%2,%3};"
        : "+f"(c[0]), "+f"(c[1]), "+f"(c[2]), "+f"(c[3])
        : "r"(a[0]), "r"(a[1]), "r"(a[2]), "r"(a[3]), "r"(b0), "r"(b1));
}

__global__ __launch_bounds__(512) void gemm_mma_kernel(const float* __restrict__ W1)
{
    extern __shared__ char smem[];
    const uint32_t sb = smem_u32(smem);
    const int tid  = threadIdx.x;
    const int wid  = tid >> 5;
    const int lane = tid & 31;

    // warp tiling: mt = wid>>2 (m16 tiles 0..3), nq = wid&3 (n32 quarters)
    const int mt = wid >> 2;
    const int nq = wid & 3;

    const uint32_t aRel = (uint32_t)((mt * 16 + (lane & 15)) * (KSTR * 2)
                                     + (lane >> 4) * 16);
    const uint32_t bRel = (uint32_t)((nq * 32 + ((lane >> 4) * 8) + (lane & 7)) * (KSTR * 2)
                                     + (((lane >> 3) & 1) * 16));

    float acc[4][4];
    #pragma unroll
    for (int nt = 0; nt < 4; nt++)
        #pragma unroll
        for (int j = 0; j < 4; j++) acc[nt][j] = 0.0f;

    for (int slab = 0; slab < 2; slab++) {
        const int d0 = blockIdx.x * DC + slab * 128;

        if (slab) __syncthreads();   // protect smem reuse

        // ---- fill A (64 x 128 fp16) hi/lo: straight 16B copies ----
        for (int idx = tid; idx < 64 * 16; idx += 512) {
            const int m = idx >> 4;
            const int i = idx & 15;                    // 16B chunk (8 fp16)
            const size_t src = (size_t)m * D_IN + d0 + i * 8;
            const int off = m * (KSTR * 2) + i * 16;
            *reinterpret_cast<uint4*>(smem + OFF_AH + off) =
                *reinterpret_cast<const uint4*>(&g_phiH[src]);
            *reinterpret_cast<uint4*>(smem + OFF_AL + off) =
                *reinterpret_cast<const uint4*>(&g_phiL[src]);
        }

        // ---- fill B^T (128 n x 128 k): B[n][k] = W1[d0+k][n], single fp16 ----
        for (int idx = tid; idx < 64 * 128; idx += 512) {
            const int kk = idx >> 7;
            const int n  = idx & 127;
            const float v0 = __ldg(&W1[(size_t)(d0 + 2 * kk)     * HG_ + n]);
            const float v1 = __ldg(&W1[(size_t)(d0 + 2 * kk + 1) * HG_ + n]);
            __half2 hp; hp.x = __float2half_rn(v0); hp.y = __float2half_rn(v1);
            const int off = n * (KSTR * 2) + kk * 4;
            *reinterpret_cast<uint32_t*>(smem + OFF_B + off) =
                *reinterpret_cast<uint32_t*>(&hp);
        }
        __syncthreads();

        // ---- 2 compensated passes, B fragments loaded once per kt ----
        const uint32_t aBaseH = sb + OFF_AH + aRel;
        const uint32_t aBaseL = sb + OFF_AL + aRel;
        const uint32_t bBase  = sb + OFF_B  + bRel;
        #pragma unroll
        for (int kt = 0; kt < 8; kt++) {
            uint32_t ah[4], al[4];
            ldsm_x4(ah, aBaseH + kt * 32);
            ldsm_x4(al, aBaseL + kt * 32);
            #pragma unroll
            for (int np = 0; np < 2; np++) {
                uint32_t bq[4];
                ldsm_x4(bq, bBase + np * 16 * (KSTR * 2) + kt * 32);
                mma_fp16(acc[np * 2 + 0], ah, bq[0], bq[1]);
                mma_fp16(acc[np * 2 + 1], ah, bq[2], bq[3]);
                mma_fp16(acc[np * 2 + 0], al, bq[0], bq[1]);
                mma_fp16(acc[np * 2 + 1], al, bq[2], bq[3]);
            }
        }
    }

    // ---- epilogue: write 64x128 partial tile ----
    float* part = &g_part[(size_t)blockIdx.x * (B_ * HG_)];
    const int qid = lane >> 2;
    const int tq  = lane & 3;
    const int row0 = mt * 16 + qid;
    #pragma unroll
    for (int nt = 0; nt < 4; nt++) {
        const int col = nq * 32 + nt * 8 + tq * 2;
        float2 v0; v0.x = acc[nt][0]; v0.y = acc[nt][1];
        float2 v1; v1.x = acc[nt][2]; v1.y = acc[nt][3];
        *reinterpret_cast<float2*>(part + row0 * HG_ + col) = v0;
        *reinterpret_cast<float2*>(part + (row0 + 8) * HG_ + col) = v1;
    }
}

// ---------------------------------------------------------------------------
// Kernel 3: reduce partials + bias + relu + l-branch.
// ---------------------------------------------------------------------------
__global__ __launch_bounds__(512) void finalize_kernel(
    const float* __restrict__ l, const float* __restrict__ b1,
    const float* __restrict__ W2, const float* __restrict__ b2,
    float* __restrict__ out)
{
    __shared__ float red[4][HG_];
    const int b = blockIdx.x;
    const int tid = threadIdx.x;
    const int h = tid & 127;
    const int p = tid >> 7;

    float s = 0.0f;
    #pragma unroll 9
    for (int c = p; c < NCHUNK; c += 4)
        s += g_part[(size_t)c * (B_ * HG_) + b * HG_ + h];
    red[p][h] = s;
    __syncthreads();

    if (p == 0) {
        const float v = red[0][h] + red[1][h] + red[2][h] + red[3][h] + b1[h];
        out[b * (HG_ + HL_) + h] = fmaxf(v, 0.0f);
        const float lw = l[b * 2 + 0] * W2[h] + l[b * 2 + 1] * W2[HL_ + h] + b2[h];
        out[b * (HG_ + HL_) + HG_ + h] = fmaxf(lw, 0.0f);
    }
}

// ---------------------------------------------------------------------------
extern "C" void kernel_launch(void* const* d_in, const int* in_sizes, int n_in,
                              void* d_out, int out_size)
{
    const float* x  = (const float*)d_in[0];
    const float* l  = (const float*)d_in[1];
    const float* W1 = (const float*)d_in[2];
    const float* b1 = (const float*)d_in[3];
    const float* W2 = (const float*)d_in[4];
    const float* b2 = (const float*)d_in[5];
    float* out = (float*)d_out;

    static bool attr_set = false;
    if (!attr_set) {
        cudaFuncSetAttribute(gemm_mma_kernel,
                             cudaFuncAttributeMaxDynamicSharedMemorySize, SMEM_GEMM);
        attr_set = true;
    }

    dim3 eg(G_, B_);
    extract_kernel<<<eg, 192>>>(x, l);
    gemm_mma_kernel<<<NCHUNK, 512, SMEM_GEMM>>>(W1);
    finalize_kernel<<<B_, 512>>>(l, b1, W2, b2, out);
}

// round 12
// speedup vs baseline: 1.1480x; 1.0779x over previous
#include <cuda_runtime.h>
#include <cuda_fp16.h>
#include <cstdint>

// Problem constants
#define B_     64
#define H_     512
#define W_     512
#define C_     3
#define G_     64
#define K_     3
#define D_IN   (K_*G_*G_*C_)   // 36864
#define HG_    128
#define HL_    128

// GEMM split-K config
#define NCHUNK 144
#define DC     256             // K-dims per CTA chunk (NCHUNK*DC == D_IN)

// Scratch (device globals)
__device__ __half g_phiH[(size_t)B_ * D_IN];          // 4.7 MB
__device__ __half g_phiL[(size_t)B_ * D_IN];          // 4.7 MB
__device__ __half g_W1h[(size_t)D_IN * HG_];          // 9.4 MB (fp16 W1)
__device__ float g_part[(size_t)NCHUNK * B_ * HG_];   // 4.7 MB

__device__ __forceinline__ uint32_t smem_u32(const void* p) {
    uint32_t a;
    asm("{ .reg .u64 t; cvta.to.shared.u64 t, %1; cvt.u32.u64 %0, t; }"
        : "=r"(a) : "l"(p));
    return a;
}

__device__ __forceinline__ void store_phi(size_t off, float v) {
    __half h = __float2half_rn(v);
    __half e = __float2half_rn(v - __half2float(h));
    g_phiH[off] = h;
    g_phiL[off] = e;
}

// ---------------------------------------------------------------------------
// Kernel 1: fused multi-scale glimpse extraction + avg pooling (R9 structure)
// + appended W1 fp32->fp16 convert blocks (by >= 64): extract is latency-bound
// at 36% DRAM, so the streaming convert rides in the utilization hole.
// Grid (64, 80): by<64 extract (b=by); by>=64 convert chunk of W1.
// ---------------------------------------------------------------------------
__global__ __launch_bounds__(192) void extract_kernel(
    const float* __restrict__ x, const float* __restrict__ l,
    const float* __restrict__ W1)
{
    const int tid = threadIdx.x;

    if (blockIdx.y >= 64) {
        // ---- W1 convert: 1024 chunks x 4608 elements ----
        const int chunk = (blockIdx.y - 64) * 64 + blockIdx.x;   // 0..1023
        const size_t base = (size_t)chunk * 4608;
        #pragma unroll
        for (int j = 0; j < 6; j++) {
            const size_t idx = base + j * 768 + tid * 4;
            const float4 v = *reinterpret_cast<const float4*>(&W1[idx]);
            __half2 p0; p0.x = __float2half_rn(v.x); p0.y = __float2half_rn(v.y);
            __half2 p1; p1.x = __float2half_rn(v.z); p1.y = __float2half_rn(v.w);
            uint2 out;
            out.x = *reinterpret_cast<uint32_t*>(&p0);
            out.y = *reinterpret_cast<uint32_t*>(&p1);
            *reinterpret_cast<uint2*>(&g_W1h[idx]) = out;
        }
        return;
    }

    __shared__ float buf[4 * 768];

    const int gy2 = blockIdx.x;
    const int b   = blockIdx.y;

    // denormalize coords exactly like reference: trunc((0.5*(l+1))*512)
    const float lx = __ldg(&l[b * 2 + 0]);
    const float ly = __ldg(&l[b * 2 + 1]);
    const int cx = (int)((0.5f * (lx + 1.0f)) * 512.0f);
    const int cy = (int)((0.5f * (ly + 1.0f)) * 512.0f);
    const int xs = cx - 128;
    const int ys = cy - 128 + gy2 * 4;

    const int jlo = (xs < 0 ? -xs : 0) * 3;
    const int xe  = xs + 256;
    const int jhi = ((xe > W_ ? W_ : xe) - xs) * 3;

    // stage 4 contiguous source rows (zero-filled OOB), scalar loads
    #pragma unroll
    for (int rr = 0; rr < 4; rr++) {
        const int y = ys + rr;
        const bool yok = (y >= 0) && (y < H_);
        const float* rowp = x + (((size_t)b * H_ + y) * W_ + xs) * C_;
        #pragma unroll
        for (int it = 0; it < 4; it++) {
            const int j = tid + it * 192;
            float v = 0.0f;
            if (yok && j >= jlo && j < jhi) v = __ldg(rowp + j);
            buf[rr * 768 + j] = v;
        }
    }
    __syncthreads();

    const int gx = tid / 3;
    const int c  = tid - gx * 3;
    const size_t phiB = (size_t)b * D_IN;

    // ---- k=2: pool 4x4 ----
    {
        float sum = 0.0f;
        #pragma unroll
        for (int dy = 0; dy < 4; dy++)
            #pragma unroll
            for (int dx = 0; dx < 4; dx++)
                sum += buf[dy * 768 + (gx * 4 + dx) * 3 + c];
        store_phi(phiB + (2 * G_ + gy2) * (G_ * C_) + tid, sum * (1.0f / 16.0f));
    }

    // ---- k=1: two output rows, pool 2x2 over central 128 cols ----
    if (gy2 >= 16 && gy2 < 48) {
        #pragma unroll
        for (int h = 0; h < 2; h++) {
            const int gy1 = 2 * gy2 - 32 + h;
            float sum = 0.0f;
            #pragma unroll
            for (int dy = 0; dy < 2; dy++)
                #pragma unroll
                for (int dx = 0; dx < 2; dx++)
                    sum += buf[(2 * h + dy) * 768 + (64 + gx * 2 + dx) * 3 + c];
            store_phi(phiB + (G_ + gy1) * (G_ * C_) + tid, sum * 0.25f);
        }
    }

    // ---- k=0: four output rows, direct copy of central 64 cols ----
    if (gy2 >= 24 && gy2 < 40) {
        #pragma unroll
        for (int rr = 0; rr < 4; rr++) {
            const int gy0 = 4 * gy2 - 96 + rr;
            store_phi(phiB + gy0 * (G_ * C_) + tid, buf[rr * 768 + (96 + gx) * 3 + c]);
        }
    }
}

// ---------------------------------------------------------------------------
// Kernel 2: split-K GEMM via mma.sync fp16, 2-pass compensated:
// D = Ah*B + Al*B. B now read from pre-converted fp16 g_W1h (half the bytes,
// PRMT-based transpose pack instead of fp32 cvt chains).
// Grid 144, 512 threads (16 warps, warp = 16m x 32n). DC=256 as 2 slabs.
// ---------------------------------------------------------------------------
#define KSTR   136                       // padded K stride in fp16 (272B rows)
#define A_TILE (64 * KSTR * 2)           // 17408 B
#define B_TILE (128 * KSTR * 2)          // 34816 B
#define OFF_AH 0
#define OFF_AL A_TILE
#define OFF_B  (2 * A_TILE)
#define SMEM_GEMM (2 * A_TILE + B_TILE)  // 69632 B

__device__ __forceinline__ void ldsm_x4(uint32_t a[4], uint32_t addr) {
    asm volatile("ldmatrix.sync.aligned.m8n8.x4.shared.b16 {%0,%1,%2,%3}, [%4];"
                 : "=r"(a[0]), "=r"(a[1]), "=r"(a[2]), "=r"(a[3]) : "r"(addr));
}
__device__ __forceinline__ void mma_fp16(
    float c[4], const uint32_t a[4], uint32_t b0, uint32_t b1)
{
    asm volatile(
        "mma.sync.aligned.m16n8k16.row.col.f32.f16.f16.f32 "
        "{%0,%1,%2,%3}, {%4,%5,%6,%7}, {%8,%9}, {%0,%1,%2,%3};"
        : "+f"(c[0]), "+f"(c[1]), "+f"(c[2]), "+f"(c[3])
        : "r"(a[0]), "r"(a[1]), "r"(a[2]), "r"(a[3]), "r"(b0), "r"(b1));
}

__global__ __launch_bounds__(512) void gemm_mma_kernel()
{
    extern __shared__ char smem[];
    const uint32_t sb = smem_u32(smem);
    const int tid  = threadIdx.x;
    const int wid  = tid >> 5;
    const int lane = tid & 31;

    // warp tiling: mt = wid>>2 (m16 tiles 0..3), nq = wid&3 (n32 quarters)
    const int mt = wid >> 2;
    const int nq = wid & 3;

    const uint32_t aRel = (uint32_t)((mt * 16 + (lane & 15)) * (KSTR * 2)
                                     + (lane >> 4) * 16);
    const uint32_t bRel = (uint32_t)((nq * 32 + ((lane >> 4) * 8) + (lane & 7)) * (KSTR * 2)
                                     + (((lane >> 3) & 1) * 16));

    float acc[4][4];
    #pragma unroll
    for (int nt = 0; nt < 4; nt++)
        #pragma unroll
        for (int j = 0; j < 4; j++) acc[nt][j] = 0.0f;

    for (int slab = 0; slab < 2; slab++) {
        const int d0 = blockIdx.x * DC + slab * 128;

        if (slab) __syncthreads();   // protect smem reuse

        // ---- fill A (64 x 128 fp16) hi/lo: straight 16B copies ----
        for (int idx = tid; idx < 64 * 16; idx += 512) {
            const int m = idx >> 4;
            const int i = idx & 15;                    // 16B chunk (8 fp16)
            const size_t src = (size_t)m * D_IN + d0 + i * 8;
            const int off = m * (KSTR * 2) + i * 16;
            *reinterpret_cast<uint4*>(smem + OFF_AH + off) =
                *reinterpret_cast<const uint4*>(&g_phiH[src]);
            *reinterpret_cast<uint4*>(smem + OFF_AL + off) =
                *reinterpret_cast<const uint4*>(&g_phiL[src]);
        }

        // ---- fill B^T (128 n x 128 k) from fp16 g_W1h [k][n]:
        //      per iter: 4 n-cols of one k-pair via 2x LDG.64 + 4x PRMT ----
        for (int idx = tid; idx < 64 * 32; idx += 512) {
            const int kk = idx >> 5;             // k-pair: k = 2*kk
            const int n0 = (idx & 31) * 4;
            const uint2 rA = *reinterpret_cast<const uint2*>(
                &g_W1h[(size_t)(d0 + 2 * kk) * HG_ + n0]);
            const uint2 rB = *reinterpret_cast<const uint2*>(
                &g_W1h[(size_t)(d0 + 2 * kk + 1) * HG_ + n0]);
            const uint32_t o0 = __byte_perm(rA.x, rB.x, 0x5410);  // (n0:  k, k+1)
            const uint32_t o1 = __byte_perm(rA.x, rB.x, 0x7632);  // (n0+1)
            const uint32_t o2 = __byte_perm(rA.y, rB.y, 0x5410);  // (n0+2)
            const uint32_t o3 = __byte_perm(rA.y, rB.y, 0x7632);  // (n0+3)
            char* bp = smem + OFF_B + kk * 4;
            *reinterpret_cast<uint32_t*>(bp + (n0    ) * (KSTR * 2)) = o0;
            *reinterpret_cast<uint32_t*>(bp + (n0 + 1) * (KSTR * 2)) = o1;
            *reinterpret_cast<uint32_t*>(bp + (n0 + 2) * (KSTR * 2)) = o2;
            *reinterpret_cast<uint32_t*>(bp + (n0 + 3) * (KSTR * 2)) = o3;
        }
        __syncthreads();

        // ---- 2 compensated passes, B fragments loaded once per kt ----
        const uint32_t aBaseH = sb + OFF_AH + aRel;
        const uint32_t aBaseL = sb + OFF_AL + aRel;
        const uint32_t bBase  = sb + OFF_B  + bRel;
        #pragma unroll
        for (int kt = 0; kt < 8; kt++) {
            uint32_t ah[4], al[4];
            ldsm_x4(ah, aBaseH + kt * 32);
            ldsm_x4(al, aBaseL + kt * 32);
            #pragma unroll
            for (int np = 0; np < 2; np++) {
                uint32_t bq[4];
                ldsm_x4(bq, bBase + np * 16 * (KSTR * 2) + kt * 32);
                mma_fp16(acc[np * 2 + 0], ah, bq[0], bq[1]);
                mma_fp16(acc[np * 2 + 1], ah, bq[2], bq[3]);
                mma_fp16(acc[np * 2 + 0], al, bq[0], bq[1]);
                mma_fp16(acc[np * 2 + 1], al, bq[2], bq[3]);
            }
        }
    }

    // ---- epilogue: write 64x128 partial tile ----
    float* part = &g_part[(size_t)blockIdx.x * (B_ * HG_)];
    const int qid = lane >> 2;
    const int tq  = lane & 3;
    const int row0 = mt * 16 + qid;
    #pragma unroll
    for (int nt = 0; nt < 4; nt++) {
        const int col = nq * 32 + nt * 8 + tq * 2;
        float2 v0; v0.x = acc[nt][0]; v0.y = acc[nt][1];
        float2 v1; v1.x = acc[nt][2]; v1.y = acc[nt][3];
        *reinterpret_cast<float2*>(part + row0 * HG_ + col) = v0;
        *reinterpret_cast<float2*>(part + (row0 + 8) * HG_ + col) = v1;
    }
}

// ---------------------------------------------------------------------------
// Kernel 3: reduce partials + bias + relu + l-branch.
// ---------------------------------------------------------------------------
__global__ __launch_bounds__(512) void finalize_kernel(
    const float* __restrict__ l, const float* __restrict__ b1,
    const float* __restrict__ W2, const float* __restrict__ b2,
    float* __restrict__ out)
{
    __shared__ float red[4][HG_];
    const int b = blockIdx.x;
    const int tid = threadIdx.x;
    const int h = tid & 127;
    const int p = tid >> 7;

    float s = 0.0f;
    #pragma unroll 9
    for (int c = p; c < NCHUNK; c += 4)
        s += g_part[(size_t)c * (B_ * HG_) + b * HG_ + h];
    red[p][h] = s;
    __syncthreads();

    if (p == 0) {
        const float v = red[0][h] + red[1][h] + red[2][h] + red[3][h] + b1[h];
        out[b * (HG_ + HL_) + h] = fmaxf(v, 0.0f);
        const float lw = l[b * 2 + 0] * W2[h] + l[b * 2 + 1] * W2[HL_ + h] + b2[h];
        out[b * (HG_ + HL_) + HG_ + h] = fmaxf(lw, 0.0f);
    }
}

// ---------------------------------------------------------------------------
extern "C" void kernel_launch(void* const* d_in, const int* in_sizes, int n_in,
                              void* d_out, int out_size)
{
    const float* x  = (const float*)d_in[0];
    const float* l  = (const float*)d_in[1];
    const float* W1 = (const float*)d_in[2];
    const float* b1 = (const float*)d_in[3];
    const float* W2 = (const float*)d_in[4];
    const float* b2 = (const float*)d_in[5];
    float* out = (float*)d_out;

    static bool attr_set = false;
    if (!attr_set) {
        cudaFuncSetAttribute(gemm_mma_kernel,
                             cudaFuncAttributeMaxDynamicSharedMemorySize, SMEM_GEMM);
        attr_set = true;
    }

    dim3 eg(G_, 80);   // by<64: extract; by>=64: W1 convert (1024 chunks)
    extract_kernel<<<eg, 192>>>(x, l, W1);
    gemm_mma_kernel<<<NCHUNK, 512, SMEM_GEMM>>>();
    finalize_kernel<<<B_, 512>>>(l, b1, W2, b2, out);
}